// round 8
// baseline (speedup 1.0000x reference)
#include <cuda_runtime.h>
#include <cuda_fp16.h>
#include <cstdint>

#define N_FEATS 9
#define VOCAB   119
#define HIDDEN  128
#define MAXN    50176
#define TILE_M  128
#define HSTR    132      // padded smem stride for h tile

// Scratch (no allocations allowed).
__device__ float  g_q[MAXN * HIDDEN];
__device__ __half g_kh[MAXN * HIDDEN];
__device__ __half g_vh[MAXN * HIDDEN];
// W pre-packed into mma B-fragment order: [3][8 np][16 kc][32 lane] uint4
__device__ uint4  g_wb[3 * 8 * 16 * 32];
__device__ int    g_mask_i32;

__device__ __forceinline__ uint32_t to_tf32(float x) {
    uint32_t r;
    asm("cvt.rna.tf32.f32 %0, %1;" : "=r"(r) : "f"(x));
    return r;
}

__device__ __forceinline__ void mma_tf32(float d[4], const uint32_t a[4],
                                         uint32_t b0, uint32_t b1) {
    asm volatile(
        "mma.sync.aligned.m16n8k8.row.col.f32.tf32.tf32.f32 "
        "{%0,%1,%2,%3}, {%4,%5,%6,%7}, {%8,%9}, {%0,%1,%2,%3};"
        : "+f"(d[0]), "+f"(d[1]), "+f"(d[2]), "+f"(d[3])
        : "r"(a[0]), "r"(a[1]), "r"(a[2]), "r"(a[3]), "r"(b0), "r"(b1));
}

// ---------------------------------------------------------------------------
// Prep: pack W (tf32-rounded) into fragment order + detect mask dtype.
// ---------------------------------------------------------------------------
__global__ __launch_bounds__(512) void k_prep(
    const float* __restrict__ Wq, const float* __restrict__ Wk,
    const float* __restrict__ Wv, const unsigned char* __restrict__ mask)
{
    const int bid = blockIdx.x;
    if (bid < 24) {
        const int i    = bid * 512 + threadIdx.x;   // 0..12287
        const int lane = i & 31;
        const int kc   = (i >> 5) & 15;
        const int np   = (i >> 9) & 7;
        const int g    = i >> 12;
        const float* W = (g == 0) ? Wq : (g == 1) ? Wk : Wv;
        const int brow = lane & 3, bcol = lane >> 2;
        const int k0 = kc * 8, c0 = np * 16;
        uint4 u;
        u.x = to_tf32(W[(k0 + brow)     * 128 + c0 + bcol]);
        u.y = to_tf32(W[(k0 + brow + 4) * 128 + c0 + bcol]);
        u.z = to_tf32(W[(k0 + brow)     * 128 + c0 + bcol + 8]);
        u.w = to_tf32(W[(k0 + brow + 4) * 128 + c0 + bcol + 8]);
        g_wb[i] = u;
    } else {
        int ok = 1;
        for (int gi = threadIdx.x; gi < 1024; gi += 512)
            if (mask[gi * 4 + 1] | mask[gi * 4 + 2] | mask[gi * 4 + 3]) ok = 0;
        ok = __syncthreads_and(ok);
        if (threadIdx.x == 0) g_mask_i32 = ok;
    }
}

// ---------------------------------------------------------------------------
// Encode: AtomEncoder + 3x tf32 mma.sync GEMM. 128 nodes/CTA, 256 threads.
// q stored fp32; k,v stored fp16 (halves attn gather traffic).
// ---------------------------------------------------------------------------
__global__ __launch_bounds__(256) void k_encode_qkv(
    const int*   __restrict__ X,
    const float* __restrict__ emb,
    const float* __restrict__ bq, const float* __restrict__ bk,
    const float* __restrict__ bv, int N)
{
    extern __shared__ float smem[];
    float* sh_h = smem;                            // [128][HSTR] tf32-rounded h
    int*   sh_x = (int*)(smem + TILE_M * HSTR);    // [128][9]

    const int tid   = threadIdx.x;
    const int node0 = blockIdx.x * TILE_M;

    for (int i = tid; i < TILE_M * N_FEATS; i += 256) {
        const int node = min(node0 + i / N_FEATS, N - 1);
        sh_x[i] = X[node * N_FEATS + (i % N_FEATS)];
    }
    __syncthreads();

    for (int gi = tid; gi < TILE_M * 32; gi += 256) {
        const int node = gi >> 5;
        const int c0   = (gi & 31) * 4;
        float4 s = make_float4(0.f, 0.f, 0.f, 0.f);
#pragma unroll
        for (int f = 0; f < N_FEATS; f++) {
            const int x = sh_x[node * N_FEATS + f];
            const float4 e = *reinterpret_cast<const float4*>(
                &emb[(f * VOCAB + x) * HIDDEN + c0]);
            s.x += e.x; s.y += e.y; s.z += e.z; s.w += e.w;
        }
        float* hp = &sh_h[node * HSTR + c0];
        hp[0] = __uint_as_float(to_tf32(s.x));
        hp[1] = __uint_as_float(to_tf32(s.y));
        hp[2] = __uint_as_float(to_tf32(s.z));
        hp[3] = __uint_as_float(to_tf32(s.w));
    }
    __syncthreads();

    const int warp = tid >> 5;
    const int lane = tid & 31;
    const int m0   = warp * 16;
    const int ar   = m0 + (lane >> 2);
    const int ac   = lane & 3;

    uint32_t afrag[64];
#pragma unroll
    for (int kc = 0; kc < 16; kc++) {
        const int k0 = kc * 8;
        afrag[kc * 4 + 0] = __float_as_uint(sh_h[ar * HSTR + k0 + ac]);
        afrag[kc * 4 + 1] = __float_as_uint(sh_h[(ar + 8) * HSTR + k0 + ac]);
        afrag[kc * 4 + 2] = __float_as_uint(sh_h[ar * HSTR + k0 + ac + 4]);
        afrag[kc * 4 + 3] = __float_as_uint(sh_h[(ar + 8) * HSTR + k0 + ac + 4]);
    }

    const float* Bs[3] = {bq, bk, bv};
    const int orow0 = node0 + m0 + (lane >> 2);
    const int ocol  = (lane & 3) * 2;

    for (int g = 0; g < 3; g++) {
        const float* bias  = Bs[g];
        const float  scale = (g == 0) ? 0.25f : 1.0f;   // q scaling = 16^-0.5

#pragma unroll
        for (int np = 0; np < 8; np++) {
            float acc0[4] = {0.f, 0.f, 0.f, 0.f};
            float acc1[4] = {0.f, 0.f, 0.f, 0.f};
            const uint4* wp = &g_wb[((g * 8 + np) * 16) * 32 + lane];
#pragma unroll
            for (int kc = 0; kc < 16; kc++) {
                const uint4 b = wp[kc * 32];
                mma_tf32(acc0, &afrag[kc * 4], b.x, b.y);
                mma_tf32(acc1, &afrag[kc * 4], b.z, b.w);
            }
            const int c00 = np * 16 + ocol;
            const float bx0 = __ldg(&bias[c00]),     by0 = __ldg(&bias[c00 + 1]);
            const float bx1 = __ldg(&bias[c00 + 8]), by1 = __ldg(&bias[c00 + 9]);
            const float2 r00 = make_float2((acc0[0] + bx0) * scale, (acc0[1] + by0) * scale);
            const float2 r01 = make_float2((acc1[0] + bx1) * scale, (acc1[1] + by1) * scale);
            const float2 r10 = make_float2((acc0[2] + bx0) * scale, (acc0[3] + by0) * scale);
            const float2 r11 = make_float2((acc1[2] + bx1) * scale, (acc1[3] + by1) * scale);

            if (g == 0) {
                if (orow0 < N) {
                    float2* p = reinterpret_cast<float2*>(&g_q[orow0 * HIDDEN + c00]);
                    p[0] = r00; p[4] = r01;
                }
                if (orow0 + 8 < N) {
                    float2* p = reinterpret_cast<float2*>(&g_q[(orow0 + 8) * HIDDEN + c00]);
                    p[0] = r10; p[4] = r11;
                }
            } else {
                __half* base = (g == 1) ? g_kh : g_vh;
                if (orow0 < N) {
                    __half2* p = reinterpret_cast<__half2*>(&base[orow0 * HIDDEN + c00]);
                    p[0] = __float22half2_rn(r00);
                    p[4] = __float22half2_rn(r01);
                }
                if (orow0 + 8 < N) {
                    __half2* p = reinterpret_cast<__half2*>(&base[(orow0 + 8) * HIDDEN + c00]);
                    p[0] = __float22half2_rn(r10);
                    p[4] = __float22half2_rn(r11);
                }
            }
        }
    }
}

// ---------------------------------------------------------------------------
// Attention: one warp per node, single pass. k/v gathered as fp16 (half the
// bytes); v held in 32 regs as half4. Lane l owns dims [4l,4l+4); head dot
// reduced via 2x shfl_xor in the 4-lane group.
// ---------------------------------------------------------------------------
__global__ __launch_bounds__(256) void k_attn(
    const int*           __restrict__ nbr_idx,
    const unsigned char* __restrict__ nbr_mask,
    float*               __restrict__ out, int N)
{
    const int warp = (blockIdx.x * blockDim.x + threadIdx.x) >> 5;
    const int lane = threadIdx.x & 31;
    if (warp >= N) return;
    const int n = warp;

    const int mask_i32 = g_mask_i32;

    int      jreg = 0;
    unsigned mreg = 0;
    if (lane < 16) {
        jreg = nbr_idx[n * 16 + lane];
        mreg = mask_i32
             ? (unsigned)reinterpret_cast<const int*>(nbr_mask)[n * 16 + lane]
             : (unsigned)nbr_mask[n * 16 + lane];
    }

    const float4 q4 = reinterpret_cast<const float4*>(g_q)[n * 32 + lane];

    float sc[16];
    uint2 vb[16];
#pragma unroll
    for (int kk = 0; kk < 16; kk++) {
        const int      j = __shfl_sync(0xffffffffu, jreg, kk);
        const unsigned m = __shfl_sync(0xffffffffu, mreg, kk);
        const uint2 kr = *reinterpret_cast<const uint2*>(&g_kh[j * HIDDEN + lane * 4]);
        vb[kk]         = *reinterpret_cast<const uint2*>(&g_vh[j * HIDDEN + lane * 4]);
        const float2 k01 = __half22float2(*reinterpret_cast<const __half2*>(&kr.x));
        const float2 k23 = __half22float2(*reinterpret_cast<const __half2*>(&kr.y));
        float d = q4.x * k01.x + q4.y * k01.y + q4.z * k23.x + q4.w * k23.y;
        d += __shfl_xor_sync(0xffffffffu, d, 1);
        d += __shfl_xor_sync(0xffffffffu, d, 2);
        sc[kk] = m ? d : -1e9f;
    }

    float mx = -1e30f;
#pragma unroll
    for (int kk = 0; kk < 16; kk++) mx = fmaxf(mx, sc[kk]);
    float s = 0.f;
#pragma unroll
    for (int kk = 0; kk < 16; kk++) { sc[kk] = __expf(sc[kk] - mx); s += sc[kk]; }
    const float inv = 1.f / s;

    float4 acc = make_float4(0.f, 0.f, 0.f, 0.f);
#pragma unroll
    for (int kk = 0; kk < 16; kk++) {
        const float p = sc[kk] * inv;
        const float2 v01 = __half22float2(*reinterpret_cast<const __half2*>(&vb[kk].x));
        const float2 v23 = __half22float2(*reinterpret_cast<const __half2*>(&vb[kk].y));
        acc.x = fmaf(p, v01.x, acc.x);
        acc.y = fmaf(p, v01.y, acc.y);
        acc.z = fmaf(p, v23.x, acc.z);
        acc.w = fmaf(p, v23.y, acc.w);
    }
    reinterpret_cast<float4*>(out)[n * 32 + lane] = acc;
}

// ---------------------------------------------------------------------------
// Launch
// ---------------------------------------------------------------------------
extern "C" void kernel_launch(void* const* d_in, const int* in_sizes, int n_in,
                              void* d_out, int out_size)
{
    const int*           X        = (const int*)d_in[0];
    const int*           nbr_idx  = (const int*)d_in[1];
    const unsigned char* nbr_mask = (const unsigned char*)d_in[2];
    const float*         emb      = (const float*)d_in[3];
    const float*         Wq       = (const float*)d_in[4];
    const float*         bq       = (const float*)d_in[5];
    const float*         Wk       = (const float*)d_in[6];
    const float*         bk       = (const float*)d_in[7];
    const float*         Wv       = (const float*)d_in[8];
    const float*         bv       = (const float*)d_in[9];
    float*               out      = (float*)d_out;

    const int N = in_sizes[0] / N_FEATS;

    k_prep<<<25, 512>>>(Wq, Wk, Wv, nbr_mask);

    const int smem_bytes = (TILE_M * HSTR) * 4 + TILE_M * N_FEATS * 4;  // ~72KB
    cudaFuncSetAttribute(k_encode_qkv,
                         cudaFuncAttributeMaxDynamicSharedMemorySize, smem_bytes);

    const int grid1 = (N + TILE_M - 1) / TILE_M;
    k_encode_qkv<<<grid1, 256, smem_bytes>>>(X, emb, bq, bk, bv, N);

    const int grid2 = (N + 7) / 8;
    k_attn<<<grid2, 256>>>(nbr_idx, nbr_mask, out, N);
}

// round 14
// speedup vs baseline: 1.1990x; 1.1990x over previous
#include <cuda_runtime.h>
#include <cuda_fp16.h>
#include <cstdint>

#define N_FEATS 9
#define VOCAB   119
#define HIDDEN  128
#define MAXN    50176
#define TILE_M  128
#define HSTR    132      // padded smem stride for h tile

// Scratch (no allocations allowed).
__device__ float  g_q[MAXN * HIDDEN];
__device__ float  g_k[MAXN * HIDDEN];
__device__ float  g_v[MAXN * HIDDEN];
__device__ __half g_kh[MAXN * HIDDEN];
__device__ __half g_vh[MAXN * HIDDEN];
// W pre-packed into mma B-fragment order: [3][8 np][16 kc][32 lane] uint4
__device__ uint4  g_wb[3 * 8 * 16 * 32];
__device__ int    g_mask_i32;

__device__ __forceinline__ uint32_t to_tf32(float x) {
    uint32_t r;
    asm("cvt.rna.tf32.f32 %0, %1;" : "=r"(r) : "f"(x));
    return r;
}

__device__ __forceinline__ void mma_tf32(float d[4], const uint32_t a[4],
                                         uint32_t b0, uint32_t b1) {
    asm volatile(
        "mma.sync.aligned.m16n8k8.row.col.f32.tf32.tf32.f32 "
        "{%0,%1,%2,%3}, {%4,%5,%6,%7}, {%8,%9}, {%0,%1,%2,%3};"
        : "+f"(d[0]), "+f"(d[1]), "+f"(d[2]), "+f"(d[3])
        : "r"(a[0]), "r"(a[1]), "r"(a[2]), "r"(a[3]), "r"(b0), "r"(b1));
}

// ---------------------------------------------------------------------------
// Prep: pack W (tf32-rounded) into fragment order + detect mask dtype.
// ---------------------------------------------------------------------------
__global__ __launch_bounds__(512) void k_prep(
    const float* __restrict__ Wq, const float* __restrict__ Wk,
    const float* __restrict__ Wv, const unsigned char* __restrict__ mask)
{
    const int bid = blockIdx.x;
    if (bid < 24) {
        const int i    = bid * 512 + threadIdx.x;   // 0..12287
        const int lane = i & 31;
        const int kc   = (i >> 5) & 15;
        const int np   = (i >> 9) & 7;
        const int g    = i >> 12;
        const float* W = (g == 0) ? Wq : (g == 1) ? Wk : Wv;
        const int brow = lane & 3, bcol = lane >> 2;
        const int k0 = kc * 8, c0 = np * 16;
        uint4 u;
        u.x = to_tf32(W[(k0 + brow)     * 128 + c0 + bcol]);
        u.y = to_tf32(W[(k0 + brow + 4) * 128 + c0 + bcol]);
        u.z = to_tf32(W[(k0 + brow)     * 128 + c0 + bcol + 8]);
        u.w = to_tf32(W[(k0 + brow + 4) * 128 + c0 + bcol + 8]);
        g_wb[i] = u;
    } else {
        int ok = 1;
        for (int gi = threadIdx.x; gi < 1024; gi += 512)
            if (mask[gi * 4 + 1] | mask[gi * 4 + 2] | mask[gi * 4 + 3]) ok = 0;
        ok = __syncthreads_and(ok);
        if (threadIdx.x == 0) g_mask_i32 = ok;
    }
}

// ---------------------------------------------------------------------------
// Encode: AtomEncoder + 3x tf32 mma.sync GEMM. 128 nodes/CTA, 256 threads.
// Identical to the 129.5us version; additionally mirrors k/v to fp16 arrays
// via a small uniform-predicated block after the fp32 stores.
// ---------------------------------------------------------------------------
__global__ __launch_bounds__(256) void k_encode_qkv(
    const int*   __restrict__ X,
    const float* __restrict__ emb,
    const float* __restrict__ bq, const float* __restrict__ bk,
    const float* __restrict__ bv, int N)
{
    extern __shared__ float smem[];
    float* sh_h = smem;                            // [128][HSTR] tf32-rounded h
    int*   sh_x = (int*)(smem + TILE_M * HSTR);    // [128][9]

    const int tid   = threadIdx.x;
    const int node0 = blockIdx.x * TILE_M;

    for (int i = tid; i < TILE_M * N_FEATS; i += 256) {
        const int node = min(node0 + i / N_FEATS, N - 1);
        sh_x[i] = X[node * N_FEATS + (i % N_FEATS)];
    }
    __syncthreads();

    for (int gi = tid; gi < TILE_M * 32; gi += 256) {
        const int node = gi >> 5;
        const int c0   = (gi & 31) * 4;
        float4 s = make_float4(0.f, 0.f, 0.f, 0.f);
#pragma unroll
        for (int f = 0; f < N_FEATS; f++) {
            const int x = sh_x[node * N_FEATS + f];
            const float4 e = *reinterpret_cast<const float4*>(
                &emb[(f * VOCAB + x) * HIDDEN + c0]);
            s.x += e.x; s.y += e.y; s.z += e.z; s.w += e.w;
        }
        float* hp = &sh_h[node * HSTR + c0];
        hp[0] = __uint_as_float(to_tf32(s.x));
        hp[1] = __uint_as_float(to_tf32(s.y));
        hp[2] = __uint_as_float(to_tf32(s.z));
        hp[3] = __uint_as_float(to_tf32(s.w));
    }
    __syncthreads();

    const int warp = tid >> 5;
    const int lane = tid & 31;
    const int m0   = warp * 16;
    const int ar   = m0 + (lane >> 2);
    const int ac   = lane & 3;

    uint32_t afrag[64];
#pragma unroll
    for (int kc = 0; kc < 16; kc++) {
        const int k0 = kc * 8;
        afrag[kc * 4 + 0] = __float_as_uint(sh_h[ar * HSTR + k0 + ac]);
        afrag[kc * 4 + 1] = __float_as_uint(sh_h[(ar + 8) * HSTR + k0 + ac]);
        afrag[kc * 4 + 2] = __float_as_uint(sh_h[ar * HSTR + k0 + ac + 4]);
        afrag[kc * 4 + 3] = __float_as_uint(sh_h[(ar + 8) * HSTR + k0 + ac + 4]);
    }

    const float*  Bs[3] = {bq, bk, bv};
    float*        Os[3] = {g_q, g_k, g_v};
    __half*       Hs[3] = {g_kh, g_kh, g_vh};   // [0] unused (guarded by g != 0)
    const float   Ss[3] = {0.25f, 1.0f, 1.0f};

    const int orow0 = node0 + m0 + (lane >> 2);
    const int ocol  = (lane & 3) * 2;

    for (int g = 0; g < 3; g++) {
        const float* bias  = Bs[g];
        float*       out   = Os[g];
        const float  scale = Ss[g];

#pragma unroll
        for (int np = 0; np < 8; np++) {
            float acc0[4] = {0.f, 0.f, 0.f, 0.f};
            float acc1[4] = {0.f, 0.f, 0.f, 0.f};
            const uint4* wp = &g_wb[((g * 8 + np) * 16) * 32 + lane];
#pragma unroll
            for (int kc = 0; kc < 16; kc++) {
                const uint4 b = wp[kc * 32];
                mma_tf32(acc0, &afrag[kc * 4], b.x, b.y);
                mma_tf32(acc1, &afrag[kc * 4], b.z, b.w);
            }
            const int c00 = np * 16 + ocol;
            const float bx0 = __ldg(&bias[c00]),     by0 = __ldg(&bias[c00 + 1]);
            const float bx1 = __ldg(&bias[c00 + 8]), by1 = __ldg(&bias[c00 + 9]);
            const float2 r00 = make_float2((acc0[0] + bx0) * scale, (acc0[1] + by0) * scale);
            const float2 r01 = make_float2((acc1[0] + bx1) * scale, (acc1[1] + by1) * scale);
            const float2 r10 = make_float2((acc0[2] + bx0) * scale, (acc0[3] + by0) * scale);
            const float2 r11 = make_float2((acc1[2] + bx1) * scale, (acc1[3] + by1) * scale);

            if (orow0 < N) {
                float2* p = reinterpret_cast<float2*>(&out[orow0 * HIDDEN + c00]);
                p[0] = r00; p[4] = r01;
            }
            if (orow0 + 8 < N) {
                float2* p = reinterpret_cast<float2*>(&out[(orow0 + 8) * HIDDEN + c00]);
                p[0] = r10; p[4] = r11;
            }
            if (g != 0) {       // mirror k/v to fp16 (uniform branch)
                __half* hb = Hs[g];
                if (orow0 < N) {
                    __half2* p = reinterpret_cast<__half2*>(&hb[orow0 * HIDDEN + c00]);
                    p[0] = __float22half2_rn(r00);
                    p[4] = __float22half2_rn(r01);
                }
                if (orow0 + 8 < N) {
                    __half2* p = reinterpret_cast<__half2*>(&hb[(orow0 + 8) * HIDDEN + c00]);
                    p[0] = __float22half2_rn(r10);
                    p[4] = __float22half2_rn(r11);
                }
            }
        }
    }
}

// ---------------------------------------------------------------------------
// Attention: one warp per node, two passes (scores, then AV) — the proven
// low-register structure — with fp16 k/v gathers (half the bytes).
// ---------------------------------------------------------------------------
__global__ __launch_bounds__(256) void k_attn(
    const int*           __restrict__ nbr_idx,
    const unsigned char* __restrict__ nbr_mask,
    float*               __restrict__ out, int N)
{
    const int warp = (blockIdx.x * blockDim.x + threadIdx.x) >> 5;
    const int lane = threadIdx.x & 31;
    if (warp >= N) return;
    const int n = warp;

    const int mask_i32 = g_mask_i32;

    int      jreg = 0;
    unsigned mreg = 0;
    if (lane < 16) {
        jreg = nbr_idx[n * 16 + lane];
        mreg = mask_i32
             ? (unsigned)reinterpret_cast<const int*>(nbr_mask)[n * 16 + lane]
             : (unsigned)nbr_mask[n * 16 + lane];
    }

    const float4 q4 = reinterpret_cast<const float4*>(g_q)[n * 32 + lane];

    // Pass 1: scores (fp16 k gather, 8B per lane).
    float sc[16];
#pragma unroll
    for (int kk = 0; kk < 16; kk++) {
        const int      j = __shfl_sync(0xffffffffu, jreg, kk);
        const unsigned m = __shfl_sync(0xffffffffu, mreg, kk);
        const uint2 kr = *reinterpret_cast<const uint2*>(&g_kh[j * HIDDEN + lane * 4]);
        const float2 k01 = __half22float2(*reinterpret_cast<const __half2*>(&kr.x));
        const float2 k23 = __half22float2(*reinterpret_cast<const __half2*>(&kr.y));
        float d = q4.x * k01.x + q4.y * k01.y + q4.z * k23.x + q4.w * k23.y;
        d += __shfl_xor_sync(0xffffffffu, d, 1);
        d += __shfl_xor_sync(0xffffffffu, d, 2);
        sc[kk] = m ? d : -1e9f;
    }

    // Softmax over 16 neighbors (per head; replicated in each 4-lane group).
    float mx = -1e30f;
#pragma unroll
    for (int kk = 0; kk < 16; kk++) mx = fmaxf(mx, sc[kk]);
    float s = 0.f;
#pragma unroll
    for (int kk = 0; kk < 16; kk++) { sc[kk] = __expf(sc[kk] - mx); s += sc[kk]; }
    const float inv = 1.f / s;

    // Pass 2: AV (fp16 v gather).
    float4 acc = make_float4(0.f, 0.f, 0.f, 0.f);
#pragma unroll
    for (int kk = 0; kk < 16; kk++) {
        const int   j = __shfl_sync(0xffffffffu, jreg, kk);
        const float p = sc[kk] * inv;
        const uint2 vr = *reinterpret_cast<const uint2*>(&g_vh[j * HIDDEN + lane * 4]);
        const float2 v01 = __half22float2(*reinterpret_cast<const __half2*>(&vr.x));
        const float2 v23 = __half22float2(*reinterpret_cast<const __half2*>(&vr.y));
        acc.x = fmaf(p, v01.x, acc.x);
        acc.y = fmaf(p, v01.y, acc.y);
        acc.z = fmaf(p, v23.x, acc.z);
        acc.w = fmaf(p, v23.y, acc.w);
    }
    reinterpret_cast<float4*>(out)[n * 32 + lane] = acc;
}

// ---------------------------------------------------------------------------
// Launch
// ---------------------------------------------------------------------------
extern "C" void kernel_launch(void* const* d_in, const int* in_sizes, int n_in,
                              void* d_out, int out_size)
{
    const int*           X        = (const int*)d_in[0];
    const int*           nbr_idx  = (const int*)d_in[1];
    const unsigned char* nbr_mask = (const unsigned char*)d_in[2];
    const float*         emb      = (const float*)d_in[3];
    const float*         Wq       = (const float*)d_in[4];
    const float*         bq       = (const float*)d_in[5];
    const float*         Wk       = (const float*)d_in[6];
    const float*         bk       = (const float*)d_in[7];
    const float*         Wv       = (const float*)d_in[8];
    const float*         bv       = (const float*)d_in[9];
    float*               out      = (float*)d_out;

    const int N = in_sizes[0] / N_FEATS;

    k_prep<<<25, 512>>>(Wq, Wk, Wv, nbr_mask);

    const int smem_bytes = (TILE_M * HSTR) * 4 + TILE_M * N_FEATS * 4;  // ~72KB
    cudaFuncSetAttribute(k_encode_qkv,
                         cudaFuncAttributeMaxDynamicSharedMemorySize, smem_bytes);

    const int grid1 = (N + TILE_M - 1) / TILE_M;
    k_encode_qkv<<<grid1, 256, smem_bytes>>>(X, emb, bq, bk, bv, N);

    const int grid2 = (N + 7) / 8;
    k_attn<<<grid2, 256>>>(nbr_idx, nbr_mask, out, N);
}

// round 15
// speedup vs baseline: 1.7049x; 1.4219x over previous
#include <cuda_runtime.h>
#include <cuda_fp16.h>
#include <cstdint>

#define N_FEATS 9
#define VOCAB   119
#define HIDDEN  128
#define MAXN    50176
#define TILE_M  128
#define HSTR    132      // padded smem stride for h tile

// Scratch (no allocations allowed).
__device__ float  g_q[MAXN * HIDDEN];
__device__ float  g_k[MAXN * HIDDEN];
__device__ float  g_v[MAXN * HIDDEN];
__device__ __half g_kh[MAXN * HIDDEN];
__device__ __half g_vh[MAXN * HIDDEN];
// W pre-packed into mma B-fragment order: [3][8 np][16 kc][32 lane] uint4
__device__ uint4  g_wb[3 * 8 * 16 * 32];
__device__ int    g_mask_i32;

__device__ __forceinline__ uint32_t to_tf32(float x) {
    uint32_t r;
    asm("cvt.rna.tf32.f32 %0, %1;" : "=r"(r) : "f"(x));
    return r;
}

__device__ __forceinline__ void mma_tf32(float d[4], const uint32_t a[4],
                                         uint32_t b0, uint32_t b1) {
    asm volatile(
        "mma.sync.aligned.m16n8k8.row.col.f32.tf32.tf32.f32 "
        "{%0,%1,%2,%3}, {%4,%5,%6,%7}, {%8,%9}, {%0,%1,%2,%3};"
        : "+f"(d[0]), "+f"(d[1]), "+f"(d[2]), "+f"(d[3])
        : "r"(a[0]), "r"(a[1]), "r"(a[2]), "r"(a[3]), "r"(b0), "r"(b1));
}

// ---------------------------------------------------------------------------
// Prep: pack W (tf32-rounded) into fragment order + detect mask dtype.
// ---------------------------------------------------------------------------
__global__ __launch_bounds__(512) void k_prep(
    const float* __restrict__ Wq, const float* __restrict__ Wk,
    const float* __restrict__ Wv, const unsigned char* __restrict__ mask)
{
    const int bid = blockIdx.x;
    if (bid < 24) {
        const int i    = bid * 512 + threadIdx.x;   // 0..12287
        const int lane = i & 31;
        const int kc   = (i >> 5) & 15;
        const int np   = (i >> 9) & 7;
        const int g    = i >> 12;
        const float* W = (g == 0) ? Wq : (g == 1) ? Wk : Wv;
        const int brow = lane & 3, bcol = lane >> 2;
        const int k0 = kc * 8, c0 = np * 16;
        uint4 u;
        u.x = to_tf32(W[(k0 + brow)     * 128 + c0 + bcol]);
        u.y = to_tf32(W[(k0 + brow + 4) * 128 + c0 + bcol]);
        u.z = to_tf32(W[(k0 + brow)     * 128 + c0 + bcol + 8]);
        u.w = to_tf32(W[(k0 + brow + 4) * 128 + c0 + bcol + 8]);
        g_wb[i] = u;
    } else {
        int ok = 1;
        for (int gi = threadIdx.x; gi < 1024; gi += 512)
            if (mask[gi * 4 + 1] | mask[gi * 4 + 2] | mask[gi * 4 + 3]) ok = 0;
        ok = __syncthreads_and(ok);
        if (threadIdx.x == 0) g_mask_i32 = ok;
    }
}

// ---------------------------------------------------------------------------
// Encode: AtomEncoder + 3x tf32 mma.sync GEMM — EXACT copy of the proven
// 129.5us version (fp32 outputs only, clean epilogue).
// ---------------------------------------------------------------------------
__global__ __launch_bounds__(256) void k_encode_qkv(
    const int*   __restrict__ X,
    const float* __restrict__ emb,
    const float* __restrict__ bq, const float* __restrict__ bk,
    const float* __restrict__ bv, int N)
{
    extern __shared__ float smem[];
    float* sh_h = smem;                            // [128][HSTR] tf32-rounded h
    int*   sh_x = (int*)(smem + TILE_M * HSTR);    // [128][9]

    const int tid   = threadIdx.x;
    const int node0 = blockIdx.x * TILE_M;

    for (int i = tid; i < TILE_M * N_FEATS; i += 256) {
        const int node = min(node0 + i / N_FEATS, N - 1);
        sh_x[i] = X[node * N_FEATS + (i % N_FEATS)];
    }
    __syncthreads();

    for (int gi = tid; gi < TILE_M * 32; gi += 256) {
        const int node = gi >> 5;
        const int c0   = (gi & 31) * 4;
        float4 s = make_float4(0.f, 0.f, 0.f, 0.f);
#pragma unroll
        for (int f = 0; f < N_FEATS; f++) {
            const int x = sh_x[node * N_FEATS + f];
            const float4 e = *reinterpret_cast<const float4*>(
                &emb[(f * VOCAB + x) * HIDDEN + c0]);
            s.x += e.x; s.y += e.y; s.z += e.z; s.w += e.w;
        }
        float* hp = &sh_h[node * HSTR + c0];
        hp[0] = __uint_as_float(to_tf32(s.x));
        hp[1] = __uint_as_float(to_tf32(s.y));
        hp[2] = __uint_as_float(to_tf32(s.z));
        hp[3] = __uint_as_float(to_tf32(s.w));
    }
    __syncthreads();

    const int warp = tid >> 5;
    const int lane = tid & 31;
    const int m0   = warp * 16;
    const int ar   = m0 + (lane >> 2);
    const int ac   = lane & 3;

    uint32_t afrag[64];
#pragma unroll
    for (int kc = 0; kc < 16; kc++) {
        const int k0 = kc * 8;
        afrag[kc * 4 + 0] = __float_as_uint(sh_h[ar * HSTR + k0 + ac]);
        afrag[kc * 4 + 1] = __float_as_uint(sh_h[(ar + 8) * HSTR + k0 + ac]);
        afrag[kc * 4 + 2] = __float_as_uint(sh_h[ar * HSTR + k0 + ac + 4]);
        afrag[kc * 4 + 3] = __float_as_uint(sh_h[(ar + 8) * HSTR + k0 + ac + 4]);
    }

    const float* Bs[3] = {bq, bk, bv};
    float*       Os[3] = {g_q, g_k, g_v};
    const float  Ss[3] = {0.25f, 1.0f, 1.0f};

    const int orow0 = node0 + m0 + (lane >> 2);
    const int ocol  = (lane & 3) * 2;

    for (int g = 0; g < 3; g++) {
        const float* bias  = Bs[g];
        float*       out   = Os[g];
        const float  scale = Ss[g];

#pragma unroll
        for (int np = 0; np < 8; np++) {
            float acc0[4] = {0.f, 0.f, 0.f, 0.f};
            float acc1[4] = {0.f, 0.f, 0.f, 0.f};
            const uint4* wp = &g_wb[((g * 8 + np) * 16) * 32 + lane];
#pragma unroll
            for (int kc = 0; kc < 16; kc++) {
                const uint4 b = wp[kc * 32];
                mma_tf32(acc0, &afrag[kc * 4], b.x, b.y);
                mma_tf32(acc1, &afrag[kc * 4], b.z, b.w);
            }
            const int c00 = np * 16 + ocol;
            const float bx0 = __ldg(&bias[c00]),     by0 = __ldg(&bias[c00 + 1]);
            const float bx1 = __ldg(&bias[c00 + 8]), by1 = __ldg(&bias[c00 + 9]);
            if (orow0 < N) {
                float2* p = reinterpret_cast<float2*>(&out[orow0 * HIDDEN + c00]);
                p[0] = make_float2((acc0[0] + bx0) * scale, (acc0[1] + by0) * scale);
                p[4] = make_float2((acc1[0] + bx1) * scale, (acc1[1] + by1) * scale);
            }
            if (orow0 + 8 < N) {
                float2* p = reinterpret_cast<float2*>(&out[(orow0 + 8) * HIDDEN + c00]);
                p[0] = make_float2((acc0[2] + bx0) * scale, (acc0[3] + by0) * scale);
                p[4] = make_float2((acc1[2] + bx1) * scale, (acc1[3] + by1) * scale);
            }
        }
    }
}

// ---------------------------------------------------------------------------
// Convert: g_k/g_v (fp32) -> g_kh/g_vh (fp16). Pure streaming, ~77MB.
// ---------------------------------------------------------------------------
__global__ __launch_bounds__(256) void k_convert(int total4)  // total4 = N*128/4
{
    const int i = blockIdx.x * blockDim.x + threadIdx.x;
    if (i >= total4) return;
    const float4 kv = reinterpret_cast<const float4*>(g_k)[i];
    const float4 vv = reinterpret_cast<const float4*>(g_v)[i];
    uint2 ko, vo;
    *reinterpret_cast<__half2*>(&ko.x) = __floats2half2_rn(kv.x, kv.y);
    *reinterpret_cast<__half2*>(&ko.y) = __floats2half2_rn(kv.z, kv.w);
    *reinterpret_cast<__half2*>(&vo.x) = __floats2half2_rn(vv.x, vv.y);
    *reinterpret_cast<__half2*>(&vo.y) = __floats2half2_rn(vv.z, vv.w);
    reinterpret_cast<uint2*>(g_kh)[i] = ko;
    reinterpret_cast<uint2*>(g_vh)[i] = vo;
}

// ---------------------------------------------------------------------------
// Attention: one warp per node, two passes, fp16 k/v gathers.
// ---------------------------------------------------------------------------
__global__ __launch_bounds__(256) void k_attn(
    const int*           __restrict__ nbr_idx,
    const unsigned char* __restrict__ nbr_mask,
    float*               __restrict__ out, int N)
{
    const int warp = (blockIdx.x * blockDim.x + threadIdx.x) >> 5;
    const int lane = threadIdx.x & 31;
    if (warp >= N) return;
    const int n = warp;

    const int mask_i32 = g_mask_i32;

    int      jreg = 0;
    unsigned mreg = 0;
    if (lane < 16) {
        jreg = nbr_idx[n * 16 + lane];
        mreg = mask_i32
             ? (unsigned)reinterpret_cast<const int*>(nbr_mask)[n * 16 + lane]
             : (unsigned)nbr_mask[n * 16 + lane];
    }

    const float4 q4 = reinterpret_cast<const float4*>(g_q)[n * 32 + lane];

    // Pass 1: scores (fp16 k gather, 8B per lane).
    float sc[16];
#pragma unroll
    for (int kk = 0; kk < 16; kk++) {
        const int      j = __shfl_sync(0xffffffffu, jreg, kk);
        const unsigned m = __shfl_sync(0xffffffffu, mreg, kk);
        const uint2 kr = *reinterpret_cast<const uint2*>(&g_kh[j * HIDDEN + lane * 4]);
        const float2 k01 = __half22float2(*reinterpret_cast<const __half2*>(&kr.x));
        const float2 k23 = __half22float2(*reinterpret_cast<const __half2*>(&kr.y));
        float d = q4.x * k01.x + q4.y * k01.y + q4.z * k23.x + q4.w * k23.y;
        d += __shfl_xor_sync(0xffffffffu, d, 1);
        d += __shfl_xor_sync(0xffffffffu, d, 2);
        sc[kk] = m ? d : -1e9f;
    }

    // Softmax over 16 neighbors (per head; replicated in each 4-lane group).
    float mx = -1e30f;
#pragma unroll
    for (int kk = 0; kk < 16; kk++) mx = fmaxf(mx, sc[kk]);
    float s = 0.f;
#pragma unroll
    for (int kk = 0; kk < 16; kk++) { sc[kk] = __expf(sc[kk] - mx); s += sc[kk]; }
    const float inv = 1.f / s;

    // Pass 2: AV (fp16 v gather).
    float4 acc = make_float4(0.f, 0.f, 0.f, 0.f);
#pragma unroll
    for (int kk = 0; kk < 16; kk++) {
        const int   j = __shfl_sync(0xffffffffu, jreg, kk);
        const float p = sc[kk] * inv;
        const uint2 vr = *reinterpret_cast<const uint2*>(&g_vh[j * HIDDEN + lane * 4]);
        const float2 v01 = __half22float2(*reinterpret_cast<const __half2*>(&vr.x));
        const float2 v23 = __half22float2(*reinterpret_cast<const __half2*>(&vr.y));
        acc.x = fmaf(p, v01.x, acc.x);
        acc.y = fmaf(p, v01.y, acc.y);
        acc.z = fmaf(p, v23.x, acc.z);
        acc.w = fmaf(p, v23.y, acc.w);
    }
    reinterpret_cast<float4*>(out)[n * 32 + lane] = acc;
}

// ---------------------------------------------------------------------------
// Launch
// ---------------------------------------------------------------------------
extern "C" void kernel_launch(void* const* d_in, const int* in_sizes, int n_in,
                              void* d_out, int out_size)
{
    const int*           X        = (const int*)d_in[0];
    const int*           nbr_idx  = (const int*)d_in[1];
    const unsigned char* nbr_mask = (const unsigned char*)d_in[2];
    const float*         emb      = (const float*)d_in[3];
    const float*         Wq       = (const float*)d_in[4];
    const float*         bq       = (const float*)d_in[5];
    const float*         Wk       = (const float*)d_in[6];
    const float*         bk       = (const float*)d_in[7];
    const float*         Wv       = (const float*)d_in[8];
    const float*         bv       = (const float*)d_in[9];
    float*               out      = (float*)d_out;

    const int N = in_sizes[0] / N_FEATS;

    k_prep<<<25, 512>>>(Wq, Wk, Wv, nbr_mask);

    const int smem_bytes = (TILE_M * HSTR) * 4 + TILE_M * N_FEATS * 4;  // ~72KB
    cudaFuncSetAttribute(k_encode_qkv,
                         cudaFuncAttributeMaxDynamicSharedMemorySize, smem_bytes);

    const int grid1 = (N + TILE_M - 1) / TILE_M;
    k_encode_qkv<<<grid1, 256, smem_bytes>>>(X, emb, bq, bk, bv, N);

    const int total4 = N * HIDDEN / 4;
    k_convert<<<(total4 + 255) / 256, 256>>>(total4);

    const int grid2 = (N + 7) / 8;
    k_attn<<<grid2, 256>>>(nbr_idx, nbr_mask, out, N);
}

// round 16
// speedup vs baseline: 1.9002x; 1.1146x over previous
#include <cuda_runtime.h>
#include <cuda_fp16.h>
#include <cstdint>

#define N_FEATS 9
#define VOCAB   119
#define HIDDEN  128
#define MAXN    50176
#define TILE_M  128
#define HSTR    132      // padded smem stride for h tile

// Scratch (no allocations allowed).
__device__ __half g_qh[MAXN * HIDDEN];
__device__ __half g_kh[MAXN * HIDDEN];
__device__ __half g_vh[MAXN * HIDDEN];
// W pre-packed into mma B-fragment order: [3][8 np][16 kc][32 lane] uint4
__device__ uint4  g_wb[3 * 8 * 16 * 32];
__device__ int    g_mask_i32;

__device__ __forceinline__ uint32_t to_tf32(float x) {
    uint32_t r;
    asm("cvt.rna.tf32.f32 %0, %1;" : "=r"(r) : "f"(x));
    return r;
}

__device__ __forceinline__ void mma_tf32(float d[4], const uint32_t a[4],
                                         uint32_t b0, uint32_t b1) {
    asm volatile(
        "mma.sync.aligned.m16n8k8.row.col.f32.tf32.tf32.f32 "
        "{%0,%1,%2,%3}, {%4,%5,%6,%7}, {%8,%9}, {%0,%1,%2,%3};"
        : "+f"(d[0]), "+f"(d[1]), "+f"(d[2]), "+f"(d[3])
        : "r"(a[0]), "r"(a[1]), "r"(a[2]), "r"(a[3]), "r"(b0), "r"(b1));
}

// ---------------------------------------------------------------------------
// Prep: pack W (tf32-rounded) into fragment order + detect mask dtype.
// ---------------------------------------------------------------------------
__global__ __launch_bounds__(512) void k_prep(
    const float* __restrict__ Wq, const float* __restrict__ Wk,
    const float* __restrict__ Wv, const unsigned char* __restrict__ mask)
{
    const int bid = blockIdx.x;
    if (bid < 24) {
        const int i    = bid * 512 + threadIdx.x;   // 0..12287
        const int lane = i & 31;
        const int kc   = (i >> 5) & 15;
        const int np   = (i >> 9) & 7;
        const int g    = i >> 12;
        const float* W = (g == 0) ? Wq : (g == 1) ? Wk : Wv;
        const int brow = lane & 3, bcol = lane >> 2;
        const int k0 = kc * 8, c0 = np * 16;
        uint4 u;
        u.x = to_tf32(W[(k0 + brow)     * 128 + c0 + bcol]);
        u.y = to_tf32(W[(k0 + brow + 4) * 128 + c0 + bcol]);
        u.z = to_tf32(W[(k0 + brow)     * 128 + c0 + bcol + 8]);
        u.w = to_tf32(W[(k0 + brow + 4) * 128 + c0 + bcol + 8]);
        g_wb[i] = u;
    } else {
        int ok = 1;
        for (int gi = threadIdx.x; gi < 1024; gi += 512)
            if (mask[gi * 4 + 1] | mask[gi * 4 + 2] | mask[gi * 4 + 3]) ok = 0;
        ok = __syncthreads_and(ok);
        if (threadIdx.x == 0) g_mask_i32 = ok;
    }
}

// ---------------------------------------------------------------------------
// Encode: AtomEncoder + 3x tf32 mma.sync GEMM. Structure identical to the
// proven 129.5us version; epilogue stores are uniformly fp16 (__half2) for
// all three outputs — no g-dependent branch, fewer store bytes.
// ---------------------------------------------------------------------------
__global__ __launch_bounds__(256) void k_encode_qkv(
    const int*   __restrict__ X,
    const float* __restrict__ emb,
    const float* __restrict__ bq, const float* __restrict__ bk,
    const float* __restrict__ bv, int N)
{
    extern __shared__ float smem[];
    float* sh_h = smem;                            // [128][HSTR] tf32-rounded h
    int*   sh_x = (int*)(smem + TILE_M * HSTR);    // [128][9]

    const int tid   = threadIdx.x;
    const int node0 = blockIdx.x * TILE_M;

    for (int i = tid; i < TILE_M * N_FEATS; i += 256) {
        const int node = min(node0 + i / N_FEATS, N - 1);
        sh_x[i] = X[node * N_FEATS + (i % N_FEATS)];
    }
    __syncthreads();

    for (int gi = tid; gi < TILE_M * 32; gi += 256) {
        const int node = gi >> 5;
        const int c0   = (gi & 31) * 4;
        float4 s = make_float4(0.f, 0.f, 0.f, 0.f);
#pragma unroll
        for (int f = 0; f < N_FEATS; f++) {
            const int x = sh_x[node * N_FEATS + f];
            const float4 e = *reinterpret_cast<const float4*>(
                &emb[(f * VOCAB + x) * HIDDEN + c0]);
            s.x += e.x; s.y += e.y; s.z += e.z; s.w += e.w;
        }
        float* hp = &sh_h[node * HSTR + c0];
        hp[0] = __uint_as_float(to_tf32(s.x));
        hp[1] = __uint_as_float(to_tf32(s.y));
        hp[2] = __uint_as_float(to_tf32(s.z));
        hp[3] = __uint_as_float(to_tf32(s.w));
    }
    __syncthreads();

    const int warp = tid >> 5;
    const int lane = tid & 31;
    const int m0   = warp * 16;
    const int ar   = m0 + (lane >> 2);
    const int ac   = lane & 3;

    uint32_t afrag[64];
#pragma unroll
    for (int kc = 0; kc < 16; kc++) {
        const int k0 = kc * 8;
        afrag[kc * 4 + 0] = __float_as_uint(sh_h[ar * HSTR + k0 + ac]);
        afrag[kc * 4 + 1] = __float_as_uint(sh_h[(ar + 8) * HSTR + k0 + ac]);
        afrag[kc * 4 + 2] = __float_as_uint(sh_h[ar * HSTR + k0 + ac + 4]);
        afrag[kc * 4 + 3] = __float_as_uint(sh_h[(ar + 8) * HSTR + k0 + ac + 4]);
    }

    const float* Bs[3] = {bq, bk, bv};
    __half*      Os[3] = {g_qh, g_kh, g_vh};
    const float  Ss[3] = {0.25f, 1.0f, 1.0f};

    const int orow0 = node0 + m0 + (lane >> 2);
    const int ocol  = (lane & 3) * 2;

    for (int g = 0; g < 3; g++) {
        const float* bias  = Bs[g];
        __half*      out   = Os[g];
        const float  scale = Ss[g];

#pragma unroll
        for (int np = 0; np < 8; np++) {
            float acc0[4] = {0.f, 0.f, 0.f, 0.f};
            float acc1[4] = {0.f, 0.f, 0.f, 0.f};
            const uint4* wp = &g_wb[((g * 8 + np) * 16) * 32 + lane];
#pragma unroll
            for (int kc = 0; kc < 16; kc++) {
                const uint4 b = wp[kc * 32];
                mma_tf32(acc0, &afrag[kc * 4], b.x, b.y);
                mma_tf32(acc1, &afrag[kc * 4], b.z, b.w);
            }
            const int c00 = np * 16 + ocol;
            const float bx0 = __ldg(&bias[c00]),     by0 = __ldg(&bias[c00 + 1]);
            const float bx1 = __ldg(&bias[c00 + 8]), by1 = __ldg(&bias[c00 + 9]);
            if (orow0 < N) {
                __half2* p = reinterpret_cast<__half2*>(&out[orow0 * HIDDEN + c00]);
                p[0] = __floats2half2_rn((acc0[0] + bx0) * scale, (acc0[1] + by0) * scale);
                p[4] = __floats2half2_rn((acc1[0] + bx1) * scale, (acc1[1] + by1) * scale);
            }
            if (orow0 + 8 < N) {
                __half2* p = reinterpret_cast<__half2*>(&out[(orow0 + 8) * HIDDEN + c00]);
                p[0] = __floats2half2_rn((acc0[2] + bx0) * scale, (acc0[3] + by0) * scale);
                p[4] = __floats2half2_rn((acc1[2] + bx1) * scale, (acc1[3] + by1) * scale);
            }
        }
    }
}

// ---------------------------------------------------------------------------
// Attention: one warp per node, two passes, fp16 q/k/v.
// ---------------------------------------------------------------------------
__global__ __launch_bounds__(256) void k_attn(
    const int*           __restrict__ nbr_idx,
    const unsigned char* __restrict__ nbr_mask,
    float*               __restrict__ out, int N)
{
    const int warp = (blockIdx.x * blockDim.x + threadIdx.x) >> 5;
    const int lane = threadIdx.x & 31;
    if (warp >= N) return;
    const int n = warp;

    const int mask_i32 = g_mask_i32;

    int      jreg = 0;
    unsigned mreg = 0;
    if (lane < 16) {
        jreg = nbr_idx[n * 16 + lane];
        mreg = mask_i32
             ? (unsigned)reinterpret_cast<const int*>(nbr_mask)[n * 16 + lane]
             : (unsigned)nbr_mask[n * 16 + lane];
    }

    const uint2 qr = *reinterpret_cast<const uint2*>(&g_qh[n * HIDDEN + lane * 4]);
    const float2 q01 = __half22float2(*reinterpret_cast<const __half2*>(&qr.x));
    const float2 q23 = __half22float2(*reinterpret_cast<const __half2*>(&qr.y));

    // Pass 1: scores (fp16 k gather, 8B per lane).
    float sc[16];
#pragma unroll
    for (int kk = 0; kk < 16; kk++) {
        const int      j = __shfl_sync(0xffffffffu, jreg, kk);
        const unsigned m = __shfl_sync(0xffffffffu, mreg, kk);
        const uint2 kr = *reinterpret_cast<const uint2*>(&g_kh[j * HIDDEN + lane * 4]);
        const float2 k01 = __half22float2(*reinterpret_cast<const __half2*>(&kr.x));
        const float2 k23 = __half22float2(*reinterpret_cast<const __half2*>(&kr.y));
        float d = q01.x * k01.x + q01.y * k01.y + q23.x * k23.x + q23.y * k23.y;
        d += __shfl_xor_sync(0xffffffffu, d, 1);
        d += __shfl_xor_sync(0xffffffffu, d, 2);
        sc[kk] = m ? d : -1e9f;
    }

    // Softmax over 16 neighbors (per head; replicated in each 4-lane group).
    float mx = -1e30f;
#pragma unroll
    for (int kk = 0; kk < 16; kk++) mx = fmaxf(mx, sc[kk]);
    float s = 0.f;
#pragma unroll
    for (int kk = 0; kk < 16; kk++) { sc[kk] = __expf(sc[kk] - mx); s += sc[kk]; }
    const float inv = 1.f / s;

    // Pass 2: AV (fp16 v gather).
    float4 acc = make_float4(0.f, 0.f, 0.f, 0.f);
#pragma unroll
    for (int kk = 0; kk < 16; kk++) {
        const int   j = __shfl_sync(0xffffffffu, jreg, kk);
        const float p = sc[kk] * inv;
        const uint2 vr = *reinterpret_cast<const uint2*>(&g_vh[j * HIDDEN + lane * 4]);
        const float2 v01 = __half22float2(*reinterpret_cast<const __half2*>(&vr.x));
        const float2 v23 = __half22float2(*reinterpret_cast<const __half2*>(&vr.y));
        acc.x = fmaf(p, v01.x, acc.x);
        acc.y = fmaf(p, v01.y, acc.y);
        acc.z = fmaf(p, v23.x, acc.z);
        acc.w = fmaf(p, v23.y, acc.w);
    }
    reinterpret_cast<float4*>(out)[n * 32 + lane] = acc;
}

// ---------------------------------------------------------------------------
// Launch
// ---------------------------------------------------------------------------
extern "C" void kernel_launch(void* const* d_in, const int* in_sizes, int n_in,
                              void* d_out, int out_size)
{
    const int*           X        = (const int*)d_in[0];
    const int*           nbr_idx  = (const int*)d_in[1];
    const unsigned char* nbr_mask = (const unsigned char*)d_in[2];
    const float*         emb      = (const float*)d_in[3];
    const float*         Wq       = (const float*)d_in[4];
    const float*         bq       = (const float*)d_in[5];
    const float*         Wk       = (const float*)d_in[6];
    const float*         bk       = (const float*)d_in[7];
    const float*         Wv       = (const float*)d_in[8];
    const float*         bv       = (const float*)d_in[9];
    float*               out      = (float*)d_out;

    const int N = in_sizes[0] / N_FEATS;

    k_prep<<<25, 512>>>(Wq, Wk, Wv, nbr_mask);

    const int smem_bytes = (TILE_M * HSTR) * 4 + TILE_M * N_FEATS * 4;  // ~72KB
    cudaFuncSetAttribute(k_encode_qkv,
                         cudaFuncAttributeMaxDynamicSharedMemorySize, smem_bytes);

    const int grid1 = (N + TILE_M - 1) / TILE_M;
    k_encode_qkv<<<grid1, 256, smem_bytes>>>(X, emb, bq, bk, bv, N);

    const int grid2 = (N + 7) / 8;
    k_attn<<<grid2, 256>>>(nbr_idx, nbr_mask, out, N);
}